// round 6
// baseline (speedup 1.0000x reference)
#include <cuda_runtime.h>

namespace {

typedef unsigned long long ull;

constexpr int H = 64, W = 64, C = 256;
constexpr int NDY = 21, NDX = 21;
constexpr int CC = 16;                 // channels per smem chunk
constexpr int S1ROW = 68;              // in1 row: plane0 @[0,32), plane1 @[34,66)
constexpr int PA   = 34;               // ≡ 2 mod 4 -> parity planes on disjoint bank residues
constexpr int S2ROW = 106;             // in2 row: plane0 @[0,52), plane1 @[54,106) (even: 8B align)
constexpr int PB   = 54;               // ≡ 2 mod 4
constexpr int NW = 3;                  // warps (dyi per block)
constexpr int S1F = CC * S1ROW;                 // 1088
constexpr int S2F = CC * S2ROW;                 // 1696
constexpr int SMF = S1F + NW * S2F;             // 6176 floats (~24.7 KB)

__device__ __forceinline__ ull ffma2(ull a, ull b, ull c) {
    ull d;
    asm("fma.rn.f32x2 %0, %1, %2, %3;" : "=l"(d) : "l"(a), "l"(b), "l"(c));
    return d;
}
__device__ __forceinline__ ull pack2(float lo, float hi) {
    ull d;
    asm("mov.b64 %0, {%1, %2};" : "=l"(d) : "f"(lo), "f"(hi));
    return d;
}
__device__ __forceinline__ void unpack2(ull v, float& lo, float& hi) {
    asm("mov.b64 {%0, %1}, %2;" : "=f"(lo), "=f"(hi) : "l"(v));
}

__global__ void __launch_bounds__(32 * NW)
corr_kernel(const float* __restrict__ in1, const float* __restrict__ in2,
            float* __restrict__ out)
{
    __shared__ __align__(16) float sm[SMF];
    float* s1 = sm;

    const int h   = blockIdx.x;
    const int dyg = blockIdx.y;
    const int b   = blockIdx.z;
    const int tid = threadIdx.x;
    const int wid = tid >> 5;
    const int t   = tid & 31;

    const int dyi = dyg * NW + wid;
    const int h2  = h + (dyi - 10) * 2;
    const bool oob = (h2 < 0) | (h2 >= H);

    float* s2c = sm + S1F + wid * S2F;

    float* outp = out + (((long)b * (NDY * NDX) + (long)dyi * NDX) * H + h) * W;

    // lane -> (j-group, parity, u-tile)
    const int jg = t >> 4;            // j0 = 10*jg (j=10 duplicated)
    const int p  = (t >> 3) & 1;
    const int bq = t & 7;             // u0 = 4*bq
    const int u0 = bq * 4;
    const int j0 = jg * 10;

    const int offA = PA * p + u0;         // + c*S1ROW (even)
    const int offB = PB * p + u0 + j0;    // + c*S2ROW (even)

    ull acc2[11][2];
#pragma unroll
    for (int jj = 0; jj < 11; ++jj) { acc2[jj][0] = 0ull; acc2[jj][1] = 0ull; }

    const float* g1 = in1 + ((long)b * C * H + h)  * W;
    const float* g2 = in2 + ((long)b * C * H + h2) * W;

    // zero s2 buffers once: pad x in [0,10)/[42,52) per plane stays zero
    for (int k = tid; k < NW * S2F; k += 32 * NW) sm[S1F + k] = 0.f;

    for (int c0 = 0; c0 < C; c0 += CC) {
        __syncthreads();
        // ---- stage s1 cooperatively: 16 rows x 16 float4 = 256 float4 over 96 threads
#pragma unroll
        for (int it = 0; it < 3; ++it) {
            int idx = tid + 96 * it;
            if (idx < 256) {
                int c = idx >> 4, i4 = idx & 15;
                float4 v = *(const float4*)(g1 + (long)(c0 + c) * (H * W) + 4 * i4);
                *(float2*)(s1 + c * S1ROW      + 2 * i4) = make_float2(v.x, v.z);
                *(float2*)(s1 + c * S1ROW + PA + 2 * i4) = make_float2(v.y, v.w);
            }
        }
        // ---- stage own s2 (STS.64, even strides)
        if (!oob) {
#pragma unroll 2
            for (int it = 0; it < 8; ++it) {
                int idx = t + 32 * it;
                int c = idx >> 4, i4 = idx & 15;
                float4 v = *(const float4*)(g2 + (long)(c0 + c) * (H * W) + 4 * i4);
                int pos = c * S2ROW + 10 + 2 * i4;
                *(float2*)(s2c + pos)      = make_float2(v.x, v.z);
                *(float2*)(s2c + pos + PB) = make_float2(v.y, v.w);
            }
        }
        __syncthreads();

        if (!oob) {
#pragma unroll 2
            for (int c = 0; c < CC; ++c) {
                const float* pa = s1  + c * S1ROW + offA;
                const float* pb = s2c + c * S2ROW + offB;
                ull A2[2];
                A2[0] = *(const ull*)pa;
                A2[1] = *(const ull*)(pa + 2);
                ull Bp[7];
#pragma unroll
                for (int m = 0; m < 7; ++m) Bp[m] = *(const ull*)(pb + 2 * m);
                float Bs[14];
#pragma unroll
                for (int m = 0; m < 7; ++m) unpack2(Bp[m], Bs[2 * m], Bs[2 * m + 1]);
                ull Bq[6];
#pragma unroll
                for (int m = 0; m < 6; ++m) Bq[m] = pack2(Bs[2 * m + 1], Bs[2 * m + 2]);
#pragma unroll
                for (int jj = 0; jj < 11; ++jj) {
#pragma unroll
                    for (int i = 0; i < 2; ++i) {
                        ull b2 = (jj & 1) ? Bq[(jj >> 1) + i] : Bp[(jj >> 1) + i];
                        acc2[jj][i] = ffma2(A2[i], b2, acc2[jj][i]);
                    }
                }
            }
        }
    }

    if (oob) {
        float4 z = make_float4(0.f, 0.f, 0.f, 0.f);
        for (int k = t; k < NDX * 16; k += 32) {
            int j = k >> 4, i4 = k & 15;
            *(float4*)(outp + (long)j * (H * W) + 4 * i4) = z;
        }
        return;
    }

    // ---- stage outputs [j][w] in own s2 buffer, coalesced store
    __syncwarp();
    float* sout = s2c;
    const float scale = 1.0f / 256.0f;
#pragma unroll
    for (int jj = 0; jj < 11; ++jj) {
        int j = j0 + jj;
#pragma unroll
        for (int i = 0; i < 2; ++i) {
            float lo, hi;
            unpack2(acc2[jj][i], lo, hi);
            sout[j * 64 + p + 2 * (u0 + 2 * i)]     = lo * scale;
            sout[j * 64 + p + 2 * (u0 + 2 * i + 1)] = hi * scale;
        }
    }
    __syncwarp();

    for (int k = t; k < NDX * 16; k += 32) {
        int j = k >> 4, i4 = k & 15;
        *(float4*)(outp + (long)j * (H * W) + 4 * i4) = *(float4*)(sout + j * 64 + 4 * i4);
    }
}

} // namespace

extern "C" void kernel_launch(void* const* d_in, const int* in_sizes, int n_in,
                              void* d_out, int out_size)
{
    const float* in1 = (const float*)d_in[0];
    const float* in2 = (const float*)d_in[1];
    float* out = (float*)d_out;
    dim3 grid(H, NDY / NW, 8);
    corr_kernel<<<grid, 32 * NW>>>(in1, in2, out);
}

// round 7
// speedup vs baseline: 1.0076x; 1.0076x over previous
#include <cuda_runtime.h>

namespace {

typedef unsigned long long ull;

constexpr int H = 64, W = 64, C = 256;
constexpr int NDY = 21, NDX = 21;
constexpr int CC = 16;                 // channels per smem chunk
constexpr int S1ROW = 68;              // in1 row: plane0 @[0,32), plane1 @[34,66)
constexpr int PA   = 34;               // ≡ 2 mod 4 -> parity planes on disjoint bank residues
constexpr int S2ROW = 106;             // in2 row: plane0 @[0,52), plane1 @[54,106) (even: 8B align)
constexpr int PB   = 54;               // ≡ 2 mod 4
constexpr int NW = 3;                  // warps (dyi per block)
constexpr int S1F = CC * S1ROW;                 // 1088
constexpr int S2F = CC * S2ROW;                 // 1696
constexpr int SMF = S1F + NW * S2F;             // 6176 floats (~24.7 KB)

__device__ __forceinline__ ull ffma2(ull a, ull b, ull c) {
    ull d;
    asm("fma.rn.f32x2 %0, %1, %2, %3;" : "=l"(d) : "l"(a), "l"(b), "l"(c));
    return d;
}
__device__ __forceinline__ ull pack2(float lo, float hi) {
    ull d;
    asm("mov.b64 %0, {%1, %2};" : "=l"(d) : "f"(lo), "f"(hi));
    return d;
}
__device__ __forceinline__ void unpack2(ull v, float& lo, float& hi) {
    asm("mov.b64 {%0, %1}, %2;" : "=f"(lo), "=f"(hi) : "l"(v));
}

__global__ void __launch_bounds__(32 * NW)
corr_kernel(const float* __restrict__ in1, const float* __restrict__ in2,
            float* __restrict__ out)
{
    __shared__ __align__(16) float sm[SMF];
    float* s1 = sm;

    const int h   = blockIdx.x;
    const int dyg = blockIdx.y;
    const int b   = blockIdx.z;
    const int tid = threadIdx.x;
    const int wid = tid >> 5;
    const int t   = tid & 31;

    const int dyi = dyg * NW + wid;
    const int h2  = h + (dyi - 10) * 2;
    const bool oob = (h2 < 0) | (h2 >= H);

    float* s2c = sm + S1F + wid * S2F;

    float* outp = out + (((long)b * (NDY * NDX) + (long)dyi * NDX) * H + h) * W;

    // lane -> (j-group, parity, u-tile)
    const int jg = t >> 4;            // j0 = 10*jg (j=10 duplicated)
    const int p  = (t >> 3) & 1;
    const int bq = t & 7;             // u0 = 4*bq
    const int u0 = bq * 4;
    const int j0 = jg * 10;

    const int offA = PA * p + u0;         // + c*S1ROW (even)
    const int offB = PB * p + u0 + j0;    // + c*S2ROW (even)

    ull acc2[11][2];
#pragma unroll
    for (int jj = 0; jj < 11; ++jj) { acc2[jj][0] = 0ull; acc2[jj][1] = 0ull; }

    const float* g1 = in1 + ((long)b * C * H + h)  * W;
    const float* g2 = in2 + ((long)b * C * H + h2) * W;

    // zero s2 buffers once: pad x in [0,10)/[42,52) per plane stays zero
    for (int k = tid; k < NW * S2F; k += 32 * NW) sm[S1F + k] = 0.f;

    for (int c0 = 0; c0 < C; c0 += CC) {
        __syncthreads();
        // ---- stage s1 cooperatively: 16 rows x 16 float4 = 256 float4 over 96 threads
#pragma unroll
        for (int it = 0; it < 3; ++it) {
            int idx = tid + 96 * it;
            if (idx < 256) {
                int c = idx >> 4, i4 = idx & 15;
                float4 v = *(const float4*)(g1 + (long)(c0 + c) * (H * W) + 4 * i4);
                *(float2*)(s1 + c * S1ROW      + 2 * i4) = make_float2(v.x, v.z);
                *(float2*)(s1 + c * S1ROW + PA + 2 * i4) = make_float2(v.y, v.w);
            }
        }
        // ---- stage own s2 (STS.64, even strides)
        if (!oob) {
#pragma unroll 2
            for (int it = 0; it < 8; ++it) {
                int idx = t + 32 * it;
                int c = idx >> 4, i4 = idx & 15;
                float4 v = *(const float4*)(g2 + (long)(c0 + c) * (H * W) + 4 * i4);
                int pos = c * S2ROW + 10 + 2 * i4;
                *(float2*)(s2c + pos)      = make_float2(v.x, v.z);
                *(float2*)(s2c + pos + PB) = make_float2(v.y, v.w);
            }
        }
        __syncthreads();

        if (!oob) {
#pragma unroll 2
            for (int c = 0; c < CC; ++c) {
                const float* pa = s1  + c * S1ROW + offA;
                const float* pb = s2c + c * S2ROW + offB;
                ull A2[2];
                A2[0] = *(const ull*)pa;
                A2[1] = *(const ull*)(pa + 2);
                ull Bp[7];
#pragma unroll
                for (int m = 0; m < 7; ++m) Bp[m] = *(const ull*)(pb + 2 * m);
                float Bs[14];
#pragma unroll
                for (int m = 0; m < 7; ++m) unpack2(Bp[m], Bs[2 * m], Bs[2 * m + 1]);
                ull Bq[6];
#pragma unroll
                for (int m = 0; m < 6; ++m) Bq[m] = pack2(Bs[2 * m + 1], Bs[2 * m + 2]);
#pragma unroll
                for (int jj = 0; jj < 11; ++jj) {
#pragma unroll
                    for (int i = 0; i < 2; ++i) {
                        ull b2 = (jj & 1) ? Bq[(jj >> 1) + i] : Bp[(jj >> 1) + i];
                        acc2[jj][i] = ffma2(A2[i], b2, acc2[jj][i]);
                    }
                }
            }
        }
    }

    if (oob) {
        float4 z = make_float4(0.f, 0.f, 0.f, 0.f);
        for (int k = t; k < NDX * 16; k += 32) {
            int j = k >> 4, i4 = k & 15;
            *(float4*)(outp + (long)j * (H * W) + 4 * i4) = z;
        }
        return;
    }

    // ---- stage outputs [j][w] in own s2 buffer, coalesced store
    __syncwarp();
    float* sout = s2c;
    const float scale = 1.0f / 256.0f;
#pragma unroll
    for (int jj = 0; jj < 11; ++jj) {
        int j = j0 + jj;
#pragma unroll
        for (int i = 0; i < 2; ++i) {
            float lo, hi;
            unpack2(acc2[jj][i], lo, hi);
            sout[j * 64 + p + 2 * (u0 + 2 * i)]     = lo * scale;
            sout[j * 64 + p + 2 * (u0 + 2 * i + 1)] = hi * scale;
        }
    }
    __syncwarp();

    for (int k = t; k < NDX * 16; k += 32) {
        int j = k >> 4, i4 = k & 15;
        *(float4*)(outp + (long)j * (H * W) + 4 * i4) = *(float4*)(sout + j * 64 + 4 * i4);
    }
}

} // namespace

extern "C" void kernel_launch(void* const* d_in, const int* in_sizes, int n_in,
                              void* d_out, int out_size)
{
    const float* in1 = (const float*)d_in[0];
    const float* in2 = (const float*)d_in[1];
    float* out = (float*)d_out;
    dim3 grid(H, NDY / NW, 8);
    corr_kernel<<<grid, 32 * NW>>>(in1, in2, out);
}